// round 3
// baseline (speedup 1.0000x reference)
#include <cuda_runtime.h>
#include <cuda_bf16.h>

// Box_diamond: two-layer soft-AND over 8-wide bins.
// out[b,p] = 1/(1 - log prod_m( (s_m - W2[p,m]) / s_m ))
// s_m      = 1 - log prod_l(1 - x[b,g*32+l*4+j]*W1[p,m,l]),  p = g*4+j
// R3: cp.async pipelined staging, persistent single-wave grid (W built once
// per block), tree products, -W1 folding. f32x2 packed math throughout.

#define D_TOT   4096
#define P_TOT   512
#define BLK_B   32
#define NTHREADS 256
#define NBLOCKS  592           // 148 SM x 4 resident blocks: exactly one wave
#define KMAX     37            // NBLOCKS / 16 p-tiles
#define TB_TOT   128           // 4096 / BLK_B batch tiles

typedef unsigned long long u64;

#define ONE2     0x3F8000003F800000ULL  // {1.0f, 1.0f}
#define NEGLN2_2 0xBF317218BF317218ULL  // {-ln2, -ln2}

__device__ __forceinline__ u64 fma2(u64 a, u64 b, u64 c) {
    u64 d; asm("fma.rn.f32x2 %0, %1, %2, %3;" : "=l"(d) : "l"(a), "l"(b), "l"(c)); return d;
}
__device__ __forceinline__ u64 mul2(u64 a, u64 b) {
    u64 d; asm("mul.rn.f32x2 %0, %1, %2;" : "=l"(d) : "l"(a), "l"(b)); return d;
}
__device__ __forceinline__ u64 add2(u64 a, u64 b) {
    u64 d; asm("add.rn.f32x2 %0, %1, %2;" : "=l"(d) : "l"(a), "l"(b)); return d;
}
__device__ __forceinline__ u64 pack2(float lo, float hi) {
    u64 d; asm("mov.b64 %0, {%1, %2};" : "=l"(d) : "f"(lo), "f"(hi)); return d;
}
__device__ __forceinline__ void unpack2(float& lo, float& hi, u64 v) {
    asm("mov.b64 {%0, %1}, %2;" : "=f"(lo), "=f"(hi) : "l"(v));
}
__device__ __forceinline__ float frcp(float v) {
    float r; asm("rcp.approx.f32 %0, %1;" : "=f"(r) : "f"(v)); return r;
}
__device__ __forceinline__ float fsigmoid(float z) {
    return frcp(1.0f + __expf(-z));
}
__device__ __forceinline__ unsigned smem_u32(const void* p) {
    return (unsigned)__cvta_generic_to_shared(p);
}
__device__ __forceinline__ void cp_async16(unsigned dst, const void* src) {
    asm volatile("cp.async.ca.shared.global [%0], [%1], 16;" :: "r"(dst), "l"(src));
}
__device__ __forceinline__ void cp_commit() {
    asm volatile("cp.async.commit_group;");
}
__device__ __forceinline__ void cp_wait0() {
    asm volatile("cp.async.wait_group 0;");
}

__global__ __launch_bounds__(NTHREADS, 4)
void box_diamond_kernel(const float* __restrict__ x,
                        const float* __restrict__ t0,
                        const float* __restrict__ t1,
                        const float* __restrict__ t2,
                        float* __restrict__ out) {
    __shared__ __align__(16) float W1n[8][8][8][4];   // -W1 [g][m][l][j]  8 KB
    __shared__ __align__(16) float W2n[8][8][4];      // -W2 [g][m][j]     1 KB
    __shared__ __align__(16) float xs[BLK_B][260];    // conflict-free LDS.128

    const int tid   = threadIdx.x;
    const int tp    = blockIdx.x & 15;     // p-tile (fixed per block)
    const int kk    = blockIdx.x >> 4;     // 0..36 batch-stripe id
    const int pbase = tp * 32;

    // ---- issue cp.async for first batch tile (latency hides under W build) ----
    const int row = (tid >> 6) | 0;        // reused staging coords
    // staging: 2048 float4s, 8 per thread
    const int tb0 = kk;                    // first batch tile
    {
        const float* src0 = x + (size_t)(tb0 * BLK_B) * D_TOT + (size_t)tp * 256;
        #pragma unroll
        for (int it = 0; it < 8; it++) {
            int idx = it * NTHREADS + tid;
            int r   = idx >> 6;
            int c4  = idx & 63;
            cp_async16(smem_u32(&xs[r][c4 * 4]), src0 + (size_t)r * D_TOT + c4 * 4);
        }
        cp_commit();
    }

    // ---- build -W1 (32 p x 8 m x 8 l sigmoids, 8/thread) ----
    #pragma unroll
    for (int it = 0; it < 8; it++) {
        int idx = it * NTHREADS + tid;
        int pl  = idx >> 6;
        int rem = idx & 63;
        int m   = rem >> 3;
        int l   = rem & 7;
        float tt2 = t2[pbase + pl];
        float d = (float)(l - m);
        W1n[pl >> 2][m][l][pl & 3] = -fsigmoid(d * (tt2 - d));
    }
    // ---- build -W2 (32 p x 8 l, 1/thread) ----
    {
        int pl = tid >> 3;
        int l  = tid & 7;
        int p  = pbase + pl;
        float lf = (float)l;
        float z1 = (lf - t0[p]) * (t1[p] - lf);
        float z2 = (7.0f - t2[p] - lf) * lf;
        W2n[pl >> 2][l][pl & 3] = -fsigmoid(z1) * fsigmoid(z2);
    }

    const int tx = tid & 31;   // b_local (lanes span b -> W reads broadcast)
    const int ty = tid >> 5;   // g_local
    (void)row;

    #pragma unroll 1
    for (int tb = tb0; tb < TB_TOT; tb += KMAX) {
        const int b0 = tb * BLK_B;

        cp_wait0();
        __syncthreads();                    // xs tile ready (and W on 1st iter)

        // ---- snapshot x into packed j-pair registers ----
        u64 nx[16];
        #pragma unroll
        for (int l = 0; l < 8; l++) {
            float4 v = *reinterpret_cast<const float4*>(&xs[tx][ty * 32 + l * 4]);
            nx[l * 2]     = pack2(v.x, v.y);
            nx[l * 2 + 1] = pack2(v.z, v.w);
        }
        __syncthreads();                    // all reads done -> xs reusable

        // ---- prefetch next tile (overlaps with compute below) ----
        const int tbn = tb + KMAX;
        if (tbn < TB_TOT) {
            const float* srcn = x + (size_t)(tbn * BLK_B) * D_TOT + (size_t)tp * 256;
            #pragma unroll
            for (int it = 0; it < 8; it++) {
                int idx = it * NTHREADS + tid;
                int r   = idx >> 6;
                int c4  = idx & 63;
                cp_async16(smem_u32(&xs[r][c4 * 4]), srcn + (size_t)r * D_TOT + c4 * 4);
            }
        }
        cp_commit();                        // (empty group on last iter is fine)

        // ---- compute 4 outputs (2 j-pairs) ----
        u64 num0 = ONE2, num1 = ONE2, den0 = ONE2, den1 = ONE2;

        #pragma unroll
        for (int m = 0; m < 8; m++) {
            u64 f0[8], f1[8];
            #pragma unroll
            for (int l = 0; l < 8; l++) {
                ulonglong2 w = *reinterpret_cast<const ulonglong2*>(&W1n[ty][m][l][0]);
                f0[l] = fma2(nx[l * 2],     w.x, ONE2);   // 1 - x*W1
                f1[l] = fma2(nx[l * 2 + 1], w.y, ONE2);
            }
            // tree product, depth 3
            u64 pr0 = mul2(mul2(mul2(f0[0], f0[1]), mul2(f0[2], f0[3])),
                           mul2(mul2(f0[4], f0[5]), mul2(f0[6], f0[7])));
            u64 pr1 = mul2(mul2(mul2(f1[0], f1[1]), mul2(f1[2], f1[3])),
                           mul2(mul2(f1[4], f1[5]), mul2(f1[6], f1[7])));
            // s = 1 - ln2*lg2(pr)
            float a0, a1, a2, a3;
            unpack2(a0, a1, pr0);
            unpack2(a2, a3, pr1);
            u64 s01 = fma2(pack2(__log2f(a0), __log2f(a1)), NEGLN2_2, ONE2);
            u64 s23 = fma2(pack2(__log2f(a2), __log2f(a3)), NEGLN2_2, ONE2);
            ulonglong2 w2 = *reinterpret_cast<const ulonglong2*>(&W2n[ty][m][0]);
            num0 = mul2(num0, add2(s01, w2.x));
            num1 = mul2(num1, add2(s23, w2.y));
            den0 = mul2(den0, s01);
            den1 = mul2(den1, s23);
        }

        // ---- epilogue: out = rcp(1 - ln2*(lg2 num - lg2 den)) ----
        float n0, n1, n2, n3, d0, d1, d2, d3;
        unpack2(n0, n1, num0); unpack2(n2, n3, num1);
        unpack2(d0, d1, den0); unpack2(d2, d3, den1);
        const float LN2 = 0.6931471805599453f;
        float4 o;
        o.x = frcp(fmaf(-LN2, __log2f(n0) - __log2f(d0), 1.0f));
        o.y = frcp(fmaf(-LN2, __log2f(n1) - __log2f(d1), 1.0f));
        o.z = frcp(fmaf(-LN2, __log2f(n2) - __log2f(d2), 1.0f));
        o.w = frcp(fmaf(-LN2, __log2f(n3) - __log2f(d3), 1.0f));

        *reinterpret_cast<float4*>(out + (size_t)(b0 + tx) * P_TOT + pbase + ty * 4) = o;
    }
}

extern "C" void kernel_launch(void* const* d_in, const int* in_sizes, int n_in,
                              void* d_out, int out_size) {
    const float* x  = (const float*)d_in[0];
    const float* t0 = (const float*)d_in[1];
    const float* t1 = (const float*)d_in[2];
    const float* t2 = (const float*)d_in[3];
    float* out = (float*)d_out;

    box_diamond_kernel<<<NBLOCKS, NTHREADS>>>(x, t0, t1, t2, out);
}

// round 4
// speedup vs baseline: 1.2667x; 1.2667x over previous
#include <cuda_runtime.h>
#include <cuda_bf16.h>

// Box_diamond: two-layer soft-AND over 8-wide bins.
// out[b,p] = 1/(1 - log prod_m( (s_m - W2[p,m]) / s_m )),
// s_m = 1 - log prod_{l:|l-m|<=3} (1 - x[b,g*32+l*4+j]*W1[p,l-m]),  p=g*4+j
// W1[p,d] = sigmoid(d*(t2[p]-d)) is <=6e-6 for |d|>=4 -> truncated (err ~3e-5).
// R4: W1 in registers (7 packed pairs), thread = j-pair, no in-loop LDS for W1,
// cp.async staging, SMEM-transposed coalesced output.

#define D_TOT   4096
#define P_TOT   512
#define NTH     512

typedef unsigned long long u64;

#define ONE2     0x3F8000003F800000ULL  // {1.0f, 1.0f}
#define NEGLN2_2 0xBF317218BF317218ULL  // {-ln2, -ln2}

__device__ __forceinline__ u64 fma2(u64 a, u64 b, u64 c) {
    u64 d; asm("fma.rn.f32x2 %0, %1, %2, %3;" : "=l"(d) : "l"(a), "l"(b), "l"(c)); return d;
}
__device__ __forceinline__ u64 mul2(u64 a, u64 b) {
    u64 d; asm("mul.rn.f32x2 %0, %1, %2;" : "=l"(d) : "l"(a), "l"(b)); return d;
}
__device__ __forceinline__ u64 pack2(float lo, float hi) {
    u64 d; asm("mov.b64 %0, {%1, %2};" : "=l"(d) : "f"(lo), "f"(hi)); return d;
}
__device__ __forceinline__ void unpack2(float& lo, float& hi, u64 v) {
    asm("mov.b64 {%0, %1}, %2;" : "=f"(lo), "=f"(hi) : "l"(v));
}
__device__ __forceinline__ float frcp(float v) {
    float r; asm("rcp.approx.f32 %0, %1;" : "=f"(r) : "f"(v)); return r;
}
__device__ __forceinline__ float fsigmoid(float z) {
    return frcp(1.0f + __expf(-z));
}
__device__ __forceinline__ unsigned smem_u32(const void* p) {
    return (unsigned)__cvta_generic_to_shared(p);
}
__device__ __forceinline__ void cp_async16(unsigned dst, const void* src) {
    asm volatile("cp.async.ca.shared.global [%0], [%1], 16;" :: "r"(dst), "l"(src));
}

__global__ __launch_bounds__(NTH, 2)
void box_diamond_kernel(const float* __restrict__ x,
                        const float* __restrict__ t0,
                        const float* __restrict__ t1,
                        const float* __restrict__ t2,
                        float* __restrict__ out) {
    __shared__ __align__(16) float xs[32][260];     // staged x tile (33.3 KB)
    __shared__ __align__(8)  float w1s[8][7][4];    // -W1 [g][d+3][j]
    __shared__ __align__(8)  float w2m[8][8][4];    // 1-W2 [g][m][j]
    __shared__ __align__(8)  float os[32][34];      // output transpose buffer

    const int tid   = threadIdx.x;
    const int b0    = blockIdx.x * 32;
    const int tp    = blockIdx.y;
    const int pbase = tp * 32;

    // ---- stage x tile (32 rows x 256 floats), async ----
    #pragma unroll
    for (int it = 0; it < 4; it++) {
        int idx = it * NTH + tid;
        int r   = idx >> 6;
        int c4  = idx & 63;
        cp_async16(smem_u32(&xs[r][c4 * 4]),
                   x + (size_t)(b0 + r) * D_TOT + (size_t)tp * 256 + c4 * 4);
    }
    asm volatile("cp.async.commit_group;");

    // ---- build -W1 table: 8g x 7d x 4j (overlaps the async copy) ----
    if (tid < 224) {
        int g = tid / 28;
        int rem = tid - g * 28;
        int d = rem >> 2;
        int j = rem & 3;
        float t2v = t2[pbase + g * 4 + j];
        float dd  = (float)(d - 3);
        w1s[g][d][j] = -fsigmoid(dd * (t2v - dd));
    }
    // ---- build 1-W2 table: 8g x 8m x 4j ----
    if (tid < 256) {
        int g = tid >> 5;
        int m = (tid >> 2) & 7;
        int j = tid & 3;
        int p = pbase + g * 4 + j;
        float lf = (float)m;
        float z1 = (lf - t0[p]) * (t1[p] - lf);
        float z2 = (7.0f - t2[p] - lf) * lf;
        w2m[g][m][j] = 1.0f - fsigmoid(z1) * fsigmoid(z2);
    }
    asm volatile("cp.async.wait_group 0;");
    __syncthreads();

    const int lane = tid & 31;      // b_local
    const int w    = tid >> 5;      // 0..15
    const int g    = w >> 1;        // group 0..7
    const int jp   = w & 1;         // j-pair 0..1

    // ---- x snapshot: 8 packed j-pairs (LDS.64) ----
    u64 nx[8];
    #pragma unroll
    for (int l = 0; l < 8; l++)
        nx[l] = *reinterpret_cast<const u64*>(&xs[lane][g * 32 + l * 4 + jp * 2]);

    // ---- -W1 into registers (broadcast LDS.64, lane-invariant) ----
    u64 w1r[7];
    #pragma unroll
    for (int d = 0; d < 7; d++)
        w1r[d] = *reinterpret_cast<const u64*>(&w1s[g][d][jp * 2]);

    // ---- main compute: 8 m, truncated l-window ----
    u64 num = ONE2, den = ONE2;
    #pragma unroll
    for (int m = 0; m < 8; m++) {
        const int lo = (m - 3 < 0) ? 0 : m - 3;
        const int hi = (m + 3 > 7) ? 7 : m + 3;
        u64 pr = fma2(nx[lo], w1r[lo - m + 3], ONE2);   // 1 - x*W1
        #pragma unroll
        for (int l = lo + 1; l <= hi; l++)
            pr = mul2(pr, fma2(nx[l], w1r[l - m + 3], ONE2));
        float a0, a1;
        unpack2(a0, a1, pr);
        u64 lg  = pack2(__log2f(a0), __log2f(a1));
        u64 w2v = *reinterpret_cast<const u64*>(&w2m[g][m][jp * 2]);
        num = mul2(num, fma2(lg, NEGLN2_2, w2v));   // s - W2 = 1-ln(pr) - W2
        den = mul2(den, fma2(lg, NEGLN2_2, ONE2));  // s
    }

    // ---- epilogue: out = rcp(1 - ln2*(lg2 num - lg2 den)) ----
    float n0, n1, d0, d1;
    unpack2(n0, n1, num);
    unpack2(d0, d1, den);
    const float LN2 = 0.6931471805599453f;
    float2 o;
    o.x = frcp(fmaf(-LN2, __log2f(n0) - __log2f(d0), 1.0f));
    o.y = frcp(fmaf(-LN2, __log2f(n1) - __log2f(d1), 1.0f));

    // ---- transpose through SMEM for fully coalesced 128B-row stores ----
    *reinterpret_cast<float2*>(&os[lane][g * 4 + jp * 2]) = o;
    __syncthreads();

    int row = w * 2 + (lane >> 4);
    int c   = lane & 15;
    float2 v = *reinterpret_cast<const float2*>(&os[row][c * 2]);
    *reinterpret_cast<float2*>(out + (size_t)(b0 + row) * P_TOT + pbase + c * 2) = v;
}

extern "C" void kernel_launch(void* const* d_in, const int* in_sizes, int n_in,
                              void* d_out, int out_size) {
    const float* x  = (const float*)d_in[0];
    const float* t0 = (const float*)d_in[1];
    const float* t1 = (const float*)d_in[2];
    const float* t2 = (const float*)d_in[3];
    float* out = (float*)d_out;

    int B = in_sizes[0] / D_TOT;          // 4096
    dim3 grid(B / 32, P_TOT / 32);        // (128, 16) = 2048 blocks
    box_diamond_kernel<<<grid, NTH>>>(x, t0, t1, t2, out);
}

// round 5
// speedup vs baseline: 1.5099x; 1.1921x over previous
#include <cuda_runtime.h>
#include <cuda_bf16.h>

// Box_diamond: two-layer soft-AND over 8-wide bins.
// out[b,p] = 1/(1 - log prod_m( (s_m - W2[p,m]) / s_m )),
// s_m = 1 - log prod_{l:|l-m|<=3} (1 - x[..]*W1[p,l-m]),  p=g*4+j
// W1[p,d]=sigmoid(d*(t2-d)) <=6e-6 for |d|>=4 -> truncated window.
// R5: 256-thr blocks (4 resident), 2 tiles/block with cp.async.cg double
// buffering (DRAM latency hidden under compute), W1 in regs, f32x2 math.

#define D_TOT   4096
#define P_TOT   512
#define NTH     256

typedef unsigned long long u64;

#define ONE2     0x3F8000003F800000ULL  // {1.0f, 1.0f}
#define NEGLN2_2 0xBF317218BF317218ULL  // {-ln2, -ln2}

__device__ __forceinline__ u64 fma2(u64 a, u64 b, u64 c) {
    u64 d; asm("fma.rn.f32x2 %0, %1, %2, %3;" : "=l"(d) : "l"(a), "l"(b), "l"(c)); return d;
}
__device__ __forceinline__ u64 mul2(u64 a, u64 b) {
    u64 d; asm("mul.rn.f32x2 %0, %1, %2;" : "=l"(d) : "l"(a), "l"(b)); return d;
}
__device__ __forceinline__ u64 pack2(float lo, float hi) {
    u64 d; asm("mov.b64 %0, {%1, %2};" : "=l"(d) : "f"(lo), "f"(hi)); return d;
}
__device__ __forceinline__ void unpack2(float& lo, float& hi, u64 v) {
    asm("mov.b64 {%0, %1}, %2;" : "=f"(lo), "=f"(hi) : "l"(v));
}
__device__ __forceinline__ float frcp(float v) {
    float r; asm("rcp.approx.f32 %0, %1;" : "=f"(r) : "f"(v)); return r;
}
__device__ __forceinline__ float fsigmoid(float z) {
    return frcp(1.0f + __expf(-z));
}
__device__ __forceinline__ unsigned smem_u32(const void* p) {
    return (unsigned)__cvta_generic_to_shared(p);
}
__device__ __forceinline__ void cp_async16(unsigned dst, const void* src) {
    asm volatile("cp.async.cg.shared.global [%0], [%1], 16;" :: "r"(dst), "l"(src));
}
__device__ __forceinline__ void st_stream_f2(float* p, float2 v) {
    asm volatile("st.global.cs.v2.f32 [%0], {%1, %2};" :: "l"(p), "f"(v.x), "f"(v.y));
}

__global__ __launch_bounds__(NTH, 4)
void box_diamond_kernel(const float* __restrict__ x,
                        const float* __restrict__ t0,
                        const float* __restrict__ t1,
                        const float* __restrict__ t2,
                        float* __restrict__ out) {
    __shared__ __align__(16) float xs[2][32][132];  // double-buffered x tiles (33 KB)
    __shared__ __align__(8)  float w1s[4][7][4];    // -W1 [g][d+3][j]
    __shared__ __align__(8)  float w2m[4][8][4];    // 1-W2 [g][m][j]
    __shared__ __align__(8)  float os[32][18];      // output transpose buffer

    const int tid   = threadIdx.x;
    const int b0    = blockIdx.x * 64;      // two consecutive 32-row tiles
    const int by    = blockIdx.y;           // p-tile of 16
    const int pbase = by * 16;
    const float* xcol = x + (size_t)by * 128;

    // ---- prefetch tile 0 (group A) ----
    {
        const float* s0 = xcol + (size_t)b0 * D_TOT;
        #pragma unroll
        for (int it = 0; it < 4; it++) {
            int idx = it * NTH + tid;
            int r   = idx >> 5;
            int c4  = idx & 31;
            cp_async16(smem_u32(&xs[0][r][c4 * 4]), s0 + (size_t)r * D_TOT + c4 * 4);
        }
        asm volatile("cp.async.commit_group;");
    }

    // ---- build tables (overlaps copy A) ----
    if (tid < 112) {              // -W1: 16p x 7d
        int pl = tid / 7;
        int d  = tid - pl * 7;
        float t2v = t2[pbase + pl];
        float dd  = (float)(d - 3);
        w1s[pl >> 2][d][pl & 3] = -fsigmoid(dd * (t2v - dd));
    }
    if (tid < 128) {              // 1-W2: 16p x 8m
        int pl = tid >> 3;
        int m  = tid & 7;
        int p  = pbase + pl;
        float lf = (float)m;
        float z1 = (lf - t0[p]) * (t1[p] - lf);
        float z2 = (7.0f - t2[p] - lf) * lf;
        w2m[pl >> 2][m][pl & 3] = 1.0f - fsigmoid(z1) * fsigmoid(z2);
    }

    // ---- prefetch tile 1 (group B) ----
    {
        const float* s1 = xcol + (size_t)(b0 + 32) * D_TOT;
        #pragma unroll
        for (int it = 0; it < 4; it++) {
            int idx = it * NTH + tid;
            int r   = idx >> 5;
            int c4  = idx & 31;
            cp_async16(smem_u32(&xs[1][r][c4 * 4]), s1 + (size_t)r * D_TOT + c4 * 4);
        }
        asm volatile("cp.async.commit_group;");
    }

    const int lane = tid & 31;    // b_local
    const int w    = tid >> 5;    // 0..7
    const int gl   = w >> 1;      // group 0..3
    const int jp   = w & 1;       // j-pair

    // ---- wait tile 0 + tables ----
    asm volatile("cp.async.wait_group 1;");
    __syncthreads();

    // ---- -W1 into regs (broadcast) ----
    u64 w1r[7];
    #pragma unroll
    for (int d = 0; d < 7; d++)
        w1r[d] = *reinterpret_cast<const u64*>(&w1s[gl][d][jp * 2]);

    const float LN2 = 0.6931471805599453f;

    #pragma unroll
    for (int t = 0; t < 2; t++) {
        // snapshot x (8 LDS.64)
        u64 nx[8];
        #pragma unroll
        for (int l = 0; l < 8; l++)
            nx[l] = *reinterpret_cast<const u64*>(&xs[t][lane][gl * 32 + l * 4 + jp * 2]);

        // main compute: 8 m, truncated l-window
        u64 num = ONE2, den = ONE2;
        #pragma unroll
        for (int m = 0; m < 8; m++) {
            const int lo = (m - 3 < 0) ? 0 : m - 3;
            const int hi = (m + 3 > 7) ? 7 : m + 3;
            u64 pr = fma2(nx[lo], w1r[lo - m + 3], ONE2);   // 1 - x*W1
            #pragma unroll
            for (int l = lo + 1; l <= hi; l++)
                pr = mul2(pr, fma2(nx[l], w1r[l - m + 3], ONE2));
            float a0, a1;
            unpack2(a0, a1, pr);
            u64 lg  = pack2(__log2f(a0), __log2f(a1));
            u64 w2v = *reinterpret_cast<const u64*>(&w2m[gl][m][jp * 2]);
            num = mul2(num, fma2(lg, NEGLN2_2, w2v));   // s - W2
            den = mul2(den, fma2(lg, NEGLN2_2, ONE2));  // s
        }

        float n0, n1, d0, d1;
        unpack2(n0, n1, num);
        unpack2(d0, d1, den);
        float2 o;
        o.x = frcp(fmaf(-LN2, __log2f(n0) - __log2f(d0), 1.0f));
        o.y = frcp(fmaf(-LN2, __log2f(n1) - __log2f(d1), 1.0f));

        // transpose through SMEM -> coalesced stores
        *reinterpret_cast<float2*>(&os[lane][gl * 4 + jp * 2]) = o;

        if (t == 0) {
            // wait for tile 1 while finishing tile 0's store
            __syncthreads();
            int row = tid >> 3;
            int c   = tid & 7;
            float2 v = *reinterpret_cast<const float2*>(&os[row][c * 2]);
            st_stream_f2(out + (size_t)(b0 + row) * P_TOT + pbase + c * 2, v);
            asm volatile("cp.async.wait_group 0;");
            __syncthreads();
        } else {
            __syncthreads();
            int row = tid >> 3;
            int c   = tid & 7;
            float2 v = *reinterpret_cast<const float2*>(&os[row][c * 2]);
            st_stream_f2(out + (size_t)(b0 + 32 + row) * P_TOT + pbase + c * 2, v);
        }
    }
}

extern "C" void kernel_launch(void* const* d_in, const int* in_sizes, int n_in,
                              void* d_out, int out_size) {
    const float* x  = (const float*)d_in[0];
    const float* t0 = (const float*)d_in[1];
    const float* t1 = (const float*)d_in[2];
    const float* t2 = (const float*)d_in[3];
    float* out = (float*)d_out;

    int B = in_sizes[0] / D_TOT;          // 4096
    dim3 grid(B / 64, P_TOT / 16);        // (64, 32) = 2048 blocks
    box_diamond_kernel<<<grid, NTH>>>(x, t0, t1, t2, out);
}